// round 2
// baseline (speedup 1.0000x reference)
#include <cuda_runtime.h>
#include <cstdint>

#define ALPHA 0.2f
#define NB 32
#define NN 128
#define FF 64
#define CC 128
#define BN (NB*NN)
#define XS 132   // padded row stride for SMEM activation tiles

static __device__ __forceinline__ float lrelu(float x) {
    return x >= 0.0f ? x : ALPHA * x;
}

// Scratch: per-node partial products of layer 1.
// Ac[b,i,c] = feats[b,i,:64] @ W1[0:64,c] + b1[c]
// An[b,j,c] = feats[b,j,:64] @ W1[64:128,c]
__device__ float g_Ac[BN * CC];
__device__ float g_An[BN * CC];

// ---------------------------------------------------------------------------
// Kernel A: per-node layer-1 partials. grid=4096 blocks, 128 threads.
// ---------------------------------------------------------------------------
__global__ void precompute_k(const float* __restrict__ feats,
                             const float* __restrict__ W1,
                             const float* __restrict__ b1) {
    int row = blockIdx.x;          // b*N + node
    int c   = threadIdx.x;         // 0..127
    __shared__ float sf[FF];
    if (c < FF) sf[c] = feats[row * FF + c];
    __syncthreads();
    float accC = b1[c];
    float accN = 0.0f;
#pragma unroll
    for (int f = 0; f < FF; ++f) {
        float v = sf[f];
        accC = fmaf(v, W1[f * CC + c], accC);
        accN = fmaf(v, W1[(FF + f) * CC + c], accN);
    }
    g_Ac[row * CC + c] = accC;
    g_An[row * CC + c] = accN;
}

// ---------------------------------------------------------------------------
// Kernel B: one block per (b,i). Two fused 128x128x128 GEMMs + masked mean.
//   X1[j,c] = lrelu(Ac[i,c] + An[j,c])          (built in SMEM, 32-j tiles)
//   X2      = lrelu(X1 @ W2 + b2)               (full 128x128 kept in SMEM)
//   S[c]    = sum_j mask[j] * lrelu(X2 @ W3 + b3)[j,c]
//   out     = lrelu(multiply_no_nan(1/denom, m_i * S))
// 256 threads, 4x4 register tiles. Warp-uniform j rows -> LDS broadcast.
// ---------------------------------------------------------------------------
__global__ __launch_bounds__(256, 1)
void edge_mlp_k(const int* __restrict__ mask,
                const float* __restrict__ W2, const float* __restrict__ b2,
                const float* __restrict__ W3, const float* __restrict__ b3,
                float* __restrict__ out) {
    extern __shared__ float sm[];
    float* sW    = sm;                    // 128*128 = 16384
    float* sX2   = sW  + CC * CC;         // 128*XS  = 16896
    float* sX1   = sX2 + NN * XS;         // 32*XS   = 4224
    float* sCi   = sX1 + 32 * XS;         // 128
    float* sB2   = sCi + CC;              // 128
    float* sB3   = sB2 + CC;              // 128
    float* sMj   = sB3 + CC;              // 128
    float* sS    = sMj + NN;              // 128
    float* sMsum = sS  + CC;              // 1 (+3 pad)

    const int tid = threadIdx.x;
    const int bi  = blockIdx.x;           // b*N + i
    const int b   = bi >> 7;
    const int i   = bi & 127;

    // --- stage W2, biases, center vector, mask ---
    for (int idx = tid * 4; idx < CC * CC; idx += 256 * 4)
        *(float4*)&sW[idx] = *(const float4*)&W2[idx];
    if (tid < CC) {
        sCi[tid] = g_Ac[bi * CC + tid];
        sB2[tid] = b2[tid];
        sB3[tid] = b3[tid];
        sS[tid]  = 0.0f;
        sMj[tid] = (mask[b * NN + tid] != 0) ? 1.0f : 0.0f;
    }
    __syncthreads();
    if (tid == 0) {
        float s = 0.0f;
        for (int j = 0; j < NN; ++j) s += sMj[j];
        sMsum[0] = s;
    }

    const int tx = tid & 31;              // c-group: c0 = tx*4
    const int ty = tid >> 5;              // warp id = j-group: j0 = ty*4 (warp-uniform)
    const int c0 = tx * 4;
    const int j0 = ty * 4;

    // ================= pass 2: X2 = lrelu(X1 @ W2 + b2) =================
    for (int jt = 0; jt < 4; ++jt) {
        const int jb = jt * 32;
        // build X1 tile (32 x 128)
        for (int idx = tid; idx < 32 * CC; idx += 256) {
            int j = idx >> 7, c = idx & 127;
            float v = sCi[c] + g_An[(b * NN + jb + j) * CC + c];
            sX1[j * XS + c] = lrelu(v);
        }
        __syncthreads();

        float acc[4][4];
#pragma unroll
        for (int r = 0; r < 4; ++r)
#pragma unroll
            for (int u = 0; u < 4; ++u) acc[r][u] = 0.0f;

#pragma unroll 4
        for (int k = 0; k < CC; ++k) {
            float4 w = *(float4*)&sW[k * CC + c0];
            float a0 = sX1[(j0 + 0) * XS + k];
            float a1 = sX1[(j0 + 1) * XS + k];
            float a2 = sX1[(j0 + 2) * XS + k];
            float a3 = sX1[(j0 + 3) * XS + k];
            acc[0][0] = fmaf(a0, w.x, acc[0][0]);
            acc[0][1] = fmaf(a0, w.y, acc[0][1]);
            acc[0][2] = fmaf(a0, w.z, acc[0][2]);
            acc[0][3] = fmaf(a0, w.w, acc[0][3]);
            acc[1][0] = fmaf(a1, w.x, acc[1][0]);
            acc[1][1] = fmaf(a1, w.y, acc[1][1]);
            acc[1][2] = fmaf(a1, w.z, acc[1][2]);
            acc[1][3] = fmaf(a1, w.w, acc[1][3]);
            acc[2][0] = fmaf(a2, w.x, acc[2][0]);
            acc[2][1] = fmaf(a2, w.y, acc[2][1]);
            acc[2][2] = fmaf(a2, w.z, acc[2][2]);
            acc[2][3] = fmaf(a2, w.w, acc[2][3]);
            acc[3][0] = fmaf(a3, w.x, acc[3][0]);
            acc[3][1] = fmaf(a3, w.y, acc[3][1]);
            acc[3][2] = fmaf(a3, w.z, acc[3][2]);
            acc[3][3] = fmaf(a3, w.w, acc[3][3]);
        }

#pragma unroll
        for (int r = 0; r < 4; ++r) {
            float4 o;
            o.x = lrelu(acc[r][0] + sB2[c0 + 0]);
            o.y = lrelu(acc[r][1] + sB2[c0 + 1]);
            o.z = lrelu(acc[r][2] + sB2[c0 + 2]);
            o.w = lrelu(acc[r][3] + sB2[c0 + 3]);
            *(float4*)&sX2[(jb + j0 + r) * XS + c0] = o;
        }
        __syncthreads();   // protects sX1 overwrite next iter + sX2 visibility
    }

    // swap weights: W3 into sW (all pass-2 reads are behind the last sync)
    for (int idx = tid * 4; idx < CC * CC; idx += 256 * 4)
        *(float4*)&sW[idx] = *(const float4*)&W3[idx];
    __syncthreads();

    // ======= pass 3: masked sum_j of lrelu(X2 @ W3 + b3) =======
    float sumc[4] = {0.0f, 0.0f, 0.0f, 0.0f};
    for (int jt = 0; jt < 4; ++jt) {
        const int jb = jt * 32;
        float acc[4][4];
#pragma unroll
        for (int r = 0; r < 4; ++r)
#pragma unroll
            for (int u = 0; u < 4; ++u) acc[r][u] = 0.0f;

#pragma unroll 4
        for (int k = 0; k < CC; ++k) {
            float4 w = *(float4*)&sW[k * CC + c0];
            float a0 = sX2[(jb + j0 + 0) * XS + k];
            float a1 = sX2[(jb + j0 + 1) * XS + k];
            float a2 = sX2[(jb + j0 + 2) * XS + k];
            float a3 = sX2[(jb + j0 + 3) * XS + k];
            acc[0][0] = fmaf(a0, w.x, acc[0][0]);
            acc[0][1] = fmaf(a0, w.y, acc[0][1]);
            acc[0][2] = fmaf(a0, w.z, acc[0][2]);
            acc[0][3] = fmaf(a0, w.w, acc[0][3]);
            acc[1][0] = fmaf(a1, w.x, acc[1][0]);
            acc[1][1] = fmaf(a1, w.y, acc[1][1]);
            acc[1][2] = fmaf(a1, w.z, acc[1][2]);
            acc[1][3] = fmaf(a1, w.w, acc[1][3]);
            acc[2][0] = fmaf(a2, w.x, acc[2][0]);
            acc[2][1] = fmaf(a2, w.y, acc[2][1]);
            acc[2][2] = fmaf(a2, w.z, acc[2][2]);
            acc[2][3] = fmaf(a2, w.w, acc[2][3]);
            acc[3][0] = fmaf(a3, w.x, acc[3][0]);
            acc[3][1] = fmaf(a3, w.y, acc[3][1]);
            acc[3][2] = fmaf(a3, w.z, acc[3][2]);
            acc[3][3] = fmaf(a3, w.w, acc[3][3]);
        }
#pragma unroll
        for (int r = 0; r < 4; ++r) {
            float m = sMj[jb + j0 + r];
#pragma unroll
            for (int u = 0; u < 4; ++u)
                sumc[u] = fmaf(m, lrelu(acc[r][u] + sB3[c0 + u]), sumc[u]);
        }
    }
    atomicAdd(&sS[c0 + 0], sumc[0]);
    atomicAdd(&sS[c0 + 1], sumc[1]);
    atomicAdd(&sS[c0 + 2], sumc[2]);
    atomicAdd(&sS[c0 + 3], sumc[3]);
    __syncthreads();

    // ======= final masked mean + multiply_no_nan + lrelu =======
    if (tid < CC) {
        float mi  = sMj[i];
        float num = mi * sS[tid];
        float den = mi * sMsum[0];
        float o;
        if (num == 0.0f) o = 0.0f;
        else             o = num / (den == 0.0f ? 1.0f : den);
        out[bi * CC + tid] = lrelu(o);
    }
}

// ---------------------------------------------------------------------------
extern "C" void kernel_launch(void* const* d_in, const int* in_sizes, int n_in,
                              void* d_out, int out_size) {
    const float* feats = (const float*)d_in[0];
    const int*   mask  = (const int*)d_in[1];
    const float* W1    = (const float*)d_in[2];
    const float* b1    = (const float*)d_in[3];
    const float* W2    = (const float*)d_in[4];
    const float* b2    = (const float*)d_in[5];
    const float* W3    = (const float*)d_in[6];
    const float* b3    = (const float*)d_in[7];
    float* out = (float*)d_out;

    precompute_k<<<BN, 128>>>(feats, W1, b1);

    const size_t smem_bytes =
        (size_t)(CC * CC + NN * XS + 32 * XS + 3 * CC + NN + CC + 4) * sizeof(float);
    cudaFuncSetAttribute(edge_mlp_k,
                         cudaFuncAttributeMaxDynamicSharedMemorySize,
                         (int)smem_bytes);
    edge_mlp_k<<<BN, 256, smem_bytes>>>(mask, W2, b2, W3, b3, out);
}

// round 3
// speedup vs baseline: 2.0092x; 2.0092x over previous
#include <cuda_runtime.h>
#include <cstdint>

#define ALPHA 0.2f
#define NB 32
#define NN 128
#define FF 64
#define CC 128
#define BN (NB*NN)
#define SA 132   // stride for activation tiles (A-frag conflict-free)
#define SB 136   // stride for weight tiles   (B-frag conflict-free)

static __device__ __forceinline__ float lrelu(float x) {
    return x >= 0.0f ? x : ALPHA * x;
}
static __device__ __forceinline__ uint32_t f2tf(float f) {
    uint32_t u;
    asm("cvt.rna.tf32.f32 %0, %1;" : "=r"(u) : "f"(f));
    return u;
}
static __device__ __forceinline__ void mma_tf32(float c[4],
        uint32_t a0, uint32_t a1, uint32_t a2, uint32_t a3,
        uint32_t b0, uint32_t b1) {
    asm volatile(
        "mma.sync.aligned.m16n8k8.row.col.f32.tf32.tf32.f32 "
        "{%0,%1,%2,%3}, {%4,%5,%6,%7}, {%8,%9}, {%0,%1,%2,%3};\n"
        : "+f"(c[0]), "+f"(c[1]), "+f"(c[2]), "+f"(c[3])
        : "r"(a0), "r"(a1), "r"(a2), "r"(a3), "r"(b0), "r"(b1));
}

// Scratch: per-node partial products of layer 1 (fp32).
__device__ float g_Ac[BN * CC];
__device__ float g_An[BN * CC];

// ---------------------------------------------------------------------------
// Kernel A: per-node layer-1 partials.
// ---------------------------------------------------------------------------
__global__ void precompute_k(const float* __restrict__ feats,
                             const float* __restrict__ W1,
                             const float* __restrict__ b1) {
    int row = blockIdx.x;
    int c   = threadIdx.x;
    __shared__ float sf[FF];
    if (c < FF) sf[c] = feats[row * FF + c];
    __syncthreads();
    float accC = b1[c];
    float accN = 0.0f;
#pragma unroll
    for (int f = 0; f < FF; ++f) {
        float v = sf[f];
        accC = fmaf(v, W1[f * CC + c], accC);
        accN = fmaf(v, W1[(FF + f) * CC + c], accN);
    }
    g_Ac[row * CC + c] = accC;
    g_An[row * CC + c] = accN;
}

// ---------------------------------------------------------------------------
// Kernel B: one block per (b,i). tf32 tensor-core GEMMs, fused masked mean.
// ---------------------------------------------------------------------------
__global__ __launch_bounds__(256, 1)
void edge_mlp_k(const int* __restrict__ mask,
                const float* __restrict__ W2, const float* __restrict__ b2,
                const float* __restrict__ W3, const float* __restrict__ b3,
                float* __restrict__ out) {
    extern __shared__ uint32_t smu[];
    uint32_t* sW  = smu;                  // 128*136 tf32 weight (W2 then W3)
    uint32_t* sX2 = sW  + CC * SB;        // 128*132 tf32 activations
    uint32_t* sX1 = sX2 + NN * SA;        // 32*132 tf32
    float* sCi   = (float*)(sX1 + 32 * SA);
    float* sB2   = sCi + CC;
    float* sB3   = sB2 + CC;
    float* sMj   = sB3 + CC;
    float* sS    = sMj + NN;
    float* sMsum = sS  + CC;

    const int tid  = threadIdx.x;
    const int wid  = tid >> 5;
    const int lane = tid & 31;
    const int lr   = lane >> 2;   // 0..7
    const int lc   = lane & 3;    // 0..3
    const int bi   = blockIdx.x;
    const int b    = bi >> 7;
    const int i    = bi & 127;

    // --- stage W2 (cvt->tf32), biases, center vector, mask ---
    for (int idx = tid * 4; idx < CC * CC; idx += 256 * 4) {
        float4 w = *(const float4*)&W2[idx];
        int k = idx >> 7, c = idx & 127;
        uint32_t* p = &sW[k * SB + c];
        p[0] = f2tf(w.x); p[1] = f2tf(w.y); p[2] = f2tf(w.z); p[3] = f2tf(w.w);
    }
    if (tid < CC) {
        sCi[tid] = g_Ac[bi * CC + tid];
        sB2[tid] = b2[tid];
        sB3[tid] = b3[tid];
        sS[tid]  = 0.0f;
        sMj[tid] = (mask[b * NN + tid] != 0) ? 1.0f : 0.0f;
    }
    __syncthreads();
    if (tid == 0) {
        float s = 0.0f;
        for (int j = 0; j < NN; ++j) s += sMj[j];
        sMsum[0] = s;
    }

    // ================= GEMM1: X2 = lrelu(X1 @ W2 + b2) =================
    // warp grid 2(m) x 4(n) over each 32-row X1 tile; warp tile 16j x 32c
    {
        const int mh = wid & 1;
        const int ng = wid >> 1;
        const int m0 = 16 * mh;
        const int n0 = 32 * ng;

        for (int jt = 0; jt < 4; ++jt) {
            const int jb = jt * 32;
            // build X1 tile (32 x 128), tf32
            for (int idx = tid; idx < 32 * CC; idx += 256) {
                int j = idx >> 7, c = idx & 127;
                float v = lrelu(sCi[c] + g_An[(b * NN + jb + j) * CC + c]);
                sX1[j * SA + c] = f2tf(v);
            }
            __syncthreads();

            float acc[4][4];
#pragma unroll
            for (int nf = 0; nf < 4; ++nf)
#pragma unroll
                for (int u = 0; u < 4; ++u) acc[nf][u] = 0.0f;

#pragma unroll
            for (int ks = 0; ks < 16; ++ks) {
                const int k0 = 8 * ks;
                uint32_t a0 = sX1[(m0 + lr)     * SA + k0 + lc];
                uint32_t a1 = sX1[(m0 + lr + 8) * SA + k0 + lc];
                uint32_t a2 = sX1[(m0 + lr)     * SA + k0 + lc + 4];
                uint32_t a3 = sX1[(m0 + lr + 8) * SA + k0 + lc + 4];
#pragma unroll
                for (int nf = 0; nf < 4; ++nf) {
                    int n = n0 + 8 * nf + lr;
                    uint32_t b0 = sW[(k0 + lc)     * SB + n];
                    uint32_t b1 = sW[(k0 + lc + 4) * SB + n];
                    mma_tf32(acc[nf], a0, a1, a2, a3, b0, b1);
                }
            }

            // epilogue: bias + lrelu + cvt, into sX2
#pragma unroll
            for (int nf = 0; nf < 4; ++nf) {
                int cb   = n0 + 8 * nf + 2 * lc;
                int row0 = jb + m0 + lr;
                int row1 = row0 + 8;
                sX2[row0 * SA + cb    ] = f2tf(lrelu(acc[nf][0] + sB2[cb]));
                sX2[row0 * SA + cb + 1] = f2tf(lrelu(acc[nf][1] + sB2[cb + 1]));
                sX2[row1 * SA + cb    ] = f2tf(lrelu(acc[nf][2] + sB2[cb]));
                sX2[row1 * SA + cb + 1] = f2tf(lrelu(acc[nf][3] + sB2[cb + 1]));
            }
            __syncthreads();   // sX1 reuse next jt; also orders sW reads
        }
    }

    // swap weights: W3 -> sW (tf32)
    for (int idx = tid * 4; idx < CC * CC; idx += 256 * 4) {
        float4 w = *(const float4*)&W3[idx];
        int k = idx >> 7, c = idx & 127;
        uint32_t* p = &sW[k * SB + c];
        p[0] = f2tf(w.x); p[1] = f2tf(w.y); p[2] = f2tf(w.z); p[3] = f2tf(w.w);
    }
    __syncthreads();

    // ===== GEMM2: S[c] = sum_j m_j * lrelu(X2 @ W3 + b3)[j,c] =====
    // warp grid 4(m) x 2(n); warp tile 32j x 64c
    {
        const int mq = wid & 3;
        const int nh = wid >> 2;
        const int j0 = 32 * mq;
        const int n0 = 64 * nh;

        float acc[2][8][4];
#pragma unroll
        for (int mi = 0; mi < 2; ++mi)
#pragma unroll
            for (int nf = 0; nf < 8; ++nf)
#pragma unroll
                for (int u = 0; u < 4; ++u) acc[mi][nf][u] = 0.0f;

#pragma unroll
        for (int ks = 0; ks < 16; ++ks) {
            const int k0 = 8 * ks;
            uint32_t a[2][4];
#pragma unroll
            for (int mi = 0; mi < 2; ++mi) {
                int r = j0 + 16 * mi + lr;
                a[mi][0] = sX2[r       * SA + k0 + lc];
                a[mi][1] = sX2[(r + 8) * SA + k0 + lc];
                a[mi][2] = sX2[r       * SA + k0 + lc + 4];
                a[mi][3] = sX2[(r + 8) * SA + k0 + lc + 4];
            }
#pragma unroll
            for (int nf = 0; nf < 8; ++nf) {
                int n = n0 + 8 * nf + lr;
                uint32_t b0 = sW[(k0 + lc)     * SB + n];
                uint32_t b1 = sW[(k0 + lc + 4) * SB + n];
                mma_tf32(acc[0][nf], a[0][0], a[0][1], a[0][2], a[0][3], b0, b1);
                mma_tf32(acc[1][nf], a[1][0], a[1][1], a[1][2], a[1][3], b0, b1);
            }
        }

        // epilogue: bias + lrelu + mask, local row-sum, warp reduce, atomics
        float colsum[8][2];
#pragma unroll
        for (int nf = 0; nf < 8; ++nf) { colsum[nf][0] = 0.0f; colsum[nf][1] = 0.0f; }

#pragma unroll
        for (int mi = 0; mi < 2; ++mi) {
            int r0 = j0 + 16 * mi + lr;
            int r1 = r0 + 8;
            float m0v = sMj[r0];
            float m1v = sMj[r1];
#pragma unroll
            for (int nf = 0; nf < 8; ++nf) {
                int cb = n0 + 8 * nf + 2 * lc;
                colsum[nf][0] += m0v * lrelu(acc[mi][nf][0] + sB3[cb])
                               + m1v * lrelu(acc[mi][nf][2] + sB3[cb]);
                colsum[nf][1] += m0v * lrelu(acc[mi][nf][1] + sB3[cb + 1])
                               + m1v * lrelu(acc[mi][nf][3] + sB3[cb + 1]);
            }
        }
#pragma unroll
        for (int nf = 0; nf < 8; ++nf) {
#pragma unroll
            for (int o = 0; o < 2; ++o) {
                float v = colsum[nf][o];
                v += __shfl_xor_sync(0xffffffffu, v, 4);
                v += __shfl_xor_sync(0xffffffffu, v, 8);
                v += __shfl_xor_sync(0xffffffffu, v, 16);
                if (lr == 0) atomicAdd(&sS[n0 + 8 * nf + 2 * lc + o], v);
            }
        }
    }
    __syncthreads();

    // ======= final masked mean + multiply_no_nan + lrelu =======
    if (tid < CC) {
        float mi  = sMj[i];
        float num = mi * sS[tid];
        float den = mi * sMsum[0];
        float o;
        if (num == 0.0f) o = 0.0f;
        else             o = num / (den == 0.0f ? 1.0f : den);
        out[bi * CC + tid] = lrelu(o);
    }
}

// ---------------------------------------------------------------------------
extern "C" void kernel_launch(void* const* d_in, const int* in_sizes, int n_in,
                              void* d_out, int out_size) {
    const float* feats = (const float*)d_in[0];
    const int*   mask  = (const int*)d_in[1];
    const float* W1    = (const float*)d_in[2];
    const float* b1    = (const float*)d_in[3];
    const float* W2    = (const float*)d_in[4];
    const float* b2    = (const float*)d_in[5];
    const float* W3    = (const float*)d_in[6];
    const float* b3    = (const float*)d_in[7];
    float* out = (float*)d_out;

    precompute_k<<<BN, 128>>>(feats, W1, b1);

    const size_t smem_bytes =
        (size_t)(CC * SB + NN * SA + 32 * SA + 5 * CC + 4) * sizeof(uint32_t);
    cudaFuncSetAttribute(edge_mlp_k,
                         cudaFuncAttributeMaxDynamicSharedMemorySize,
                         (int)smem_bytes);
    edge_mlp_k<<<BN, 256, smem_bytes>>>(mask, W2, b2, W3, b3, out);
}

// round 4
// speedup vs baseline: 3.6807x; 1.8320x over previous
#include <cuda_runtime.h>
#include <cstdint>

#define ALPHA 0.2f
#define NB 32
#define NN 128
#define FF 64
#define CC 128
#define BN (NB*NN)

static __device__ __forceinline__ float lrelu(float x) {
    return x >= 0.0f ? x : ALPHA * x;
}
static __device__ __forceinline__ uint32_t f2tf(float f) {
    uint32_t u;
    asm("cvt.rna.tf32.f32 %0, %1;" : "=r"(u) : "f"(f));
    return u;
}
static __device__ __forceinline__ void mma_tf32(float c[4],
        uint32_t a0, uint32_t a1, uint32_t a2, uint32_t a3,
        uint32_t b0, uint32_t b1) {
    asm volatile(
        "mma.sync.aligned.m16n8k8.row.col.f32.tf32.tf32.f32 "
        "{%0,%1,%2,%3}, {%4,%5,%6,%7}, {%8,%9}, {%0,%1,%2,%3};\n"
        : "+f"(c[0]), "+f"(c[1]), "+f"(c[2]), "+f"(c[3])
        : "r"(a0), "r"(a1), "r"(a2), "r"(a3), "r"(b0), "r"(b1));
}

// Scratch
__device__ float g_Ac[BN * CC];
__device__ float g_An[BN * CC];
// Fragment-ordered tf32 weights: word idx ((ks*16+oct)*32+lane)*2 + p
//   p0 = W[(ks*8+lc)*128 + oct*8+lr], p1 = W[(ks*8+lc+4)*128 + oct*8+lr]
__device__ uint32_t g_W2f[CC * CC];
__device__ uint32_t g_W3f[CC * CC];

// ---------------------------------------------------------------------------
// Setup: permute W2/W3 into B-fragment order (runs once per launch, tiny).
// ---------------------------------------------------------------------------
__global__ void setup_wf_k(const float* __restrict__ W2,
                           const float* __restrict__ W3) {
    int t = blockIdx.x * 256 + threadIdx.x;      // 0..16383
    const float* W   = (t & 8192) ? W3 : W2;
    uint32_t*    dst = (t & 8192) ? g_W3f : g_W2f;
    int s    = t & 8191;                          // slot = (ks*16+oct)*32+lane
    int ks   = s >> 9;
    int oct  = (s >> 5) & 15;
    int lane = s & 31;
    int lr = lane >> 2, lc = lane & 3;
    uint32_t p0 = f2tf(W[(ks * 8 + lc)     * CC + oct * 8 + lr]);
    uint32_t p1 = f2tf(W[(ks * 8 + lc + 4) * CC + oct * 8 + lr]);
    dst[s * 2]     = p0;
    dst[s * 2 + 1] = p1;
}

// ---------------------------------------------------------------------------
// Per-node layer-1 partials.
// ---------------------------------------------------------------------------
__global__ void precompute_k(const float* __restrict__ feats,
                             const float* __restrict__ W1,
                             const float* __restrict__ b1) {
    int row = blockIdx.x;
    int c   = threadIdx.x;
    __shared__ float sf[FF];
    if (c < FF) sf[c] = feats[row * FF + c];
    __syncthreads();
    float accC = b1[c];
    float accN = 0.0f;
#pragma unroll
    for (int f = 0; f < FF; ++f) {
        float v = sf[f];
        accC = fmaf(v, W1[f * CC + c], accC);
        accN = fmaf(v, W1[(FF + f) * CC + c], accN);
    }
    g_Ac[row * CC + c] = accC;
    g_An[row * CC + c] = accN;
}

// ---------------------------------------------------------------------------
// Main: one block per (b,i). Fragment-ready smem, tf32 mma, fused mean.
// smem words: Bf 16384 | X2f 16384 | X1f 8192 | misc 644  (~162.5 KB)
// ---------------------------------------------------------------------------
__global__ __launch_bounds__(256, 1)
void edge_mlp_k(const int* __restrict__ mask,
                const float* __restrict__ b2,
                const float* __restrict__ b3,
                float* __restrict__ out) {
    extern __shared__ uint32_t smu[];
    uint32_t* sBf  = smu;                 // B-fragments (W2 then W3)
    uint32_t* sX2f = sBf + 16384;         // X2 in A-fragment order (8 mtiles)
    uint32_t* sX1f = sX2f + 16384;        // X1 pass tile (4 mtiles = 64 rows)
    float* sCi   = (float*)(sX1f + 8192);
    float* sB2   = sCi + 128;
    float* sB3   = sB2 + 128;
    float* sMj   = sB3 + 128;
    float* sS    = sMj + 128;
    float* sMsum = sS + 128;

    const int tid  = threadIdx.x;
    const int wid  = tid >> 5;
    const int lane = tid & 31;
    const int lr   = lane >> 2;
    const int lc   = lane & 3;
    const int bi   = blockIdx.x;
    const int b    = bi >> 7;
    const int i    = bi & 127;
    const int bbase = b * NN;

    // --- stage W2 fragments (coalesced), misc ---
    {
        const uint4* src = (const uint4*)g_W2f;
        uint4* dst = (uint4*)sBf;
#pragma unroll
        for (int u = 0; u < 16; ++u) dst[tid + u * 256] = src[tid + u * 256];
    }
    if (tid < 128) {
        sCi[tid] = g_Ac[bi * CC + tid];
        sB2[tid] = b2[tid];
        sB3[tid] = b3[tid];
        sS[tid]  = 0.0f;
        sMj[tid] = (mask[bbase + tid] != 0) ? 1.0f : 0.0f;
    }
    __syncthreads();
    if (tid == 0) {
        float s = 0.0f;
        for (int j = 0; j < NN; ++j) s += sMj[j];
        sMsum[0] = s;
    }

    // ================= GEMM1 over two 64-row passes =================
    const int mg = wid & 1;   // 32-row half within the pass
    const int ng = wid >> 1;  // 32-col group (4 octets)

    for (int p = 0; p < 2; ++p) {
        const int jb = p * 64;
        // --- build X1f (64 rows, A-fragment order) ---
#pragma unroll
        for (int u = 0; u < 8; ++u) {
            int s   = tid + u * 256;          // 0..2047
            int mt  = s >> 9;
            int ks  = (s >> 5) & 15;
            int ln  = s & 31;
            int lrs = ln >> 2, lcs = ln & 3;
            int r0 = jb + mt * 16 + lrs, r1 = r0 + 8;
            int c0 = ks * 8 + lcs,       c1 = c0 + 4;
            const float* An0 = &g_An[(bbase + r0) * CC];
            const float* An1 = &g_An[(bbase + r1) * CC];
            float ci0 = sCi[c0], ci1 = sCi[c1];
            uint4 v;
            v.x = f2tf(lrelu(ci0 + An0[c0]));
            v.y = f2tf(lrelu(ci0 + An1[c0]));
            v.z = f2tf(lrelu(ci1 + An0[c1]));
            v.w = f2tf(lrelu(ci1 + An1[c1]));
            *(uint4*)&sX1f[s * 4] = v;
        }
        __syncthreads();

        float acc[2][4][4];
#pragma unroll
        for (int mt = 0; mt < 2; ++mt)
#pragma unroll
            for (int of = 0; of < 4; ++of)
#pragma unroll
                for (int u = 0; u < 4; ++u) acc[mt][of][u] = 0.0f;

#pragma unroll 4
        for (int ks = 0; ks < 16; ++ks) {
            uint4 a0 = *(const uint4*)&sX1f[(((mg * 2 + 0) * 16 + ks) * 32 + lane) * 4];
            uint4 a1 = *(const uint4*)&sX1f[(((mg * 2 + 1) * 16 + ks) * 32 + lane) * 4];
#pragma unroll
            for (int of = 0; of < 4; ++of) {
                uint2 bb = *(const uint2*)&sBf[((ks * 16 + ng * 4 + of) * 32 + lane) * 2];
                mma_tf32(acc[0][of], a0.x, a0.y, a0.z, a0.w, bb.x, bb.y);
                mma_tf32(acc[1][of], a1.x, a1.y, a1.z, a1.w, bb.x, bb.y);
            }
        }

        // --- epilogue: bias+lrelu+cvt, write X2f in A-fragment order ---
        const int qc = 2 * (lc >= 2 ? 1 : 0);
        const int lp = lr * 4 + 2 * (lc & 1);
#pragma unroll
        for (int mt = 0; mt < 2; ++mt) {
            int gmt = p * 4 + mg * 2 + mt;
#pragma unroll
            for (int of = 0; of < 4; ++of) {
                int oct = ng * 4 + of;
                int cb  = oct * 8 + 2 * lc;
                float e0 = lrelu(acc[mt][of][0] + sB2[cb]);
                float e1 = lrelu(acc[mt][of][1] + sB2[cb + 1]);
                float e2 = lrelu(acc[mt][of][2] + sB2[cb]);
                float e3 = lrelu(acc[mt][of][3] + sB2[cb + 1]);
                uint32_t base = ((gmt * 16 + oct) * 32 + lp) * 4 + qc;
                sX2f[base]     = f2tf(e0);   // (r0, cb)
                sX2f[base + 4] = f2tf(e1);   // (r0, cb+1)
                sX2f[base + 1] = f2tf(e2);   // (r1, cb)
                sX2f[base + 5] = f2tf(e3);   // (r1, cb+1)
            }
        }
        __syncthreads();
    }

    // --- swap to W3 fragments ---
    {
        const uint4* src = (const uint4*)g_W3f;
        uint4* dst = (uint4*)sBf;
#pragma unroll
        for (int u = 0; u < 16; ++u) dst[tid + u * 256] = src[tid + u * 256];
    }
    __syncthreads();

    // ===== GEMM2: S[c] = sum_j m_j * lrelu(X2 @ W3 + b3)[j,c] =====
    {
        const int mg2 = wid & 3;   // 32-row group
        const int ng2 = wid >> 2;  // 64-col group (8 octets)

        float acc2[2][8][4];
#pragma unroll
        for (int mt = 0; mt < 2; ++mt)
#pragma unroll
            for (int of = 0; of < 8; ++of)
#pragma unroll
                for (int u = 0; u < 4; ++u) acc2[mt][of][u] = 0.0f;

#pragma unroll 4
        for (int ks = 0; ks < 16; ++ks) {
            uint4 a0 = *(const uint4*)&sX2f[(((mg2 * 2 + 0) * 16 + ks) * 32 + lane) * 4];
            uint4 a1 = *(const uint4*)&sX2f[(((mg2 * 2 + 1) * 16 + ks) * 32 + lane) * 4];
#pragma unroll
            for (int of = 0; of < 8; ++of) {
                uint2 bb = *(const uint2*)&sBf[((ks * 16 + ng2 * 8 + of) * 32 + lane) * 2];
                mma_tf32(acc2[0][of], a0.x, a0.y, a0.z, a0.w, bb.x, bb.y);
                mma_tf32(acc2[1][of], a1.x, a1.y, a1.z, a1.w, bb.x, bb.y);
            }
        }

        // --- epilogue: mask-weighted column sums ---
        float cs[8][2];
#pragma unroll
        for (int of = 0; of < 8; ++of) { cs[of][0] = 0.0f; cs[of][1] = 0.0f; }

#pragma unroll
        for (int mt = 0; mt < 2; ++mt) {
            int r0 = mg2 * 32 + mt * 16 + lr, r1 = r0 + 8;
            float m0 = sMj[r0], m1 = sMj[r1];
#pragma unroll
            for (int of = 0; of < 8; ++of) {
                int cb = (ng2 * 8 + of) * 8 + 2 * lc;
                cs[of][0] += m0 * lrelu(acc2[mt][of][0] + sB3[cb])
                           + m1 * lrelu(acc2[mt][of][2] + sB3[cb]);
                cs[of][1] += m0 * lrelu(acc2[mt][of][1] + sB3[cb + 1])
                           + m1 * lrelu(acc2[mt][of][3] + sB3[cb + 1]);
            }
        }
#pragma unroll
        for (int of = 0; of < 8; ++of) {
#pragma unroll
            for (int o = 0; o < 2; ++o) {
                float v = cs[of][o];
                v += __shfl_xor_sync(0xffffffffu, v, 4);
                v += __shfl_xor_sync(0xffffffffu, v, 8);
                v += __shfl_xor_sync(0xffffffffu, v, 16);
                if (lr == 0) atomicAdd(&sS[(ng2 * 8 + of) * 8 + 2 * lc + o], v);
            }
        }
    }
    __syncthreads();

    // ======= final masked mean + multiply_no_nan + lrelu =======
    if (tid < 128) {
        float miv = sMj[i];
        float num = miv * sS[tid];
        float den = miv * sMsum[0];
        float o;
        if (num == 0.0f) o = 0.0f;
        else             o = num / (den == 0.0f ? 1.0f : den);
        out[bi * CC + tid] = lrelu(o);
    }
}

// ---------------------------------------------------------------------------
extern "C" void kernel_launch(void* const* d_in, const int* in_sizes, int n_in,
                              void* d_out, int out_size) {
    const float* feats = (const float*)d_in[0];
    const int*   mask  = (const int*)d_in[1];
    const float* W1    = (const float*)d_in[2];
    const float* b1    = (const float*)d_in[3];
    const float* W2    = (const float*)d_in[4];
    const float* b2    = (const float*)d_in[5];
    const float* W3    = (const float*)d_in[6];
    const float* b3    = (const float*)d_in[7];
    float* out = (float*)d_out;

    setup_wf_k<<<64, 256>>>(W2, W3);
    precompute_k<<<BN, 128>>>(feats, W1, b1);

    const size_t smem_bytes =
        (size_t)(16384 + 16384 + 8192 + 5 * 128 + 4) * sizeof(uint32_t);
    cudaFuncSetAttribute(edge_mlp_k,
                         cudaFuncAttributeMaxDynamicSharedMemorySize,
                         (int)smem_bytes);
    edge_mlp_k<<<BN, 256, smem_bytes>>>(mask, b2, b3, out);
}

// round 6
// speedup vs baseline: 4.4158x; 1.1997x over previous
#include <cuda_runtime.h>
#include <cuda_fp16.h>
#include <cstdint>

#define ALPHA 0.2f
#define NB 32
#define NN 128
#define FF 64
#define CC 128
#define BN (NB*NN)

static __device__ __forceinline__ float lrelu(float x) {
    return x >= 0.0f ? x : ALPHA * x;
}
static __device__ __forceinline__ uint32_t pack2(float lo, float hi) {
    __half2 h = __floats2half2_rn(lo, hi);
    return *(uint32_t*)&h;
}
static __device__ __forceinline__ void mma_f16(float c[4],
        uint32_t a0, uint32_t a1, uint32_t a2, uint32_t a3,
        uint32_t b0, uint32_t b1) {
    asm volatile(
        "mma.sync.aligned.m16n8k16.row.col.f32.f16.f16.f32 "
        "{%0,%1,%2,%3}, {%4,%5,%6,%7}, {%8,%9}, {%0,%1,%2,%3};\n"
        : "+f"(c[0]), "+f"(c[1]), "+f"(c[2]), "+f"(c[3])
        : "r"(a0), "r"(a1), "r"(a2), "r"(a3), "r"(b0), "r"(b1));
}

// Scratch
__device__ float g_Ac[BN * CC];
__device__ float g_An[BN * CC];
// fp16x2 B-fragment-ordered weights. Slot s = (ks*16+oct)*32+lane, ks in [0,8).
//   word s*2+0 = pack(W[k0  ][col], W[k0+1][col]),  k0 = ks*16+2*lc, col = oct*8+lr
//   word s*2+1 = pack(W[k0+8][col], W[k0+9][col])
__device__ uint32_t g_W2h[CC * CC / 2];
__device__ uint32_t g_W3h[CC * CC / 2];

// ---------------------------------------------------------------------------
// Setup: permute W2/W3 into fp16 B-fragment order. 4096 slots per matrix.
// ---------------------------------------------------------------------------
__global__ void setup_wh_k(const float* __restrict__ W2,
                           const float* __restrict__ W3) {
    int t = blockIdx.x * 256 + threadIdx.x;      // 0..8191
    const float* W   = (t & 4096) ? W3 : W2;
    uint32_t*    dst = (t & 4096) ? g_W3h : g_W2h;
    int s    = t & 4095;                          // slot = (ks*16+oct)*32+lane
    int ks   = s >> 9;                            // 0..7  (k-chunk of 16)
    int oct  = (s >> 5) & 15;                     // 0..15 (8-col octet)
    int lane = s & 31;
    int lr = lane >> 2, lc = lane & 3;
    int col = oct * 8 + lr;
    int k0  = ks * 16 + 2 * lc;
    dst[s * 2]     = pack2(W[k0 * CC + col],       W[(k0 + 1) * CC + col]);
    dst[s * 2 + 1] = pack2(W[(k0 + 8) * CC + col], W[(k0 + 9) * CC + col]);
}

// ---------------------------------------------------------------------------
// Per-node layer-1 partials (fp32).
// ---------------------------------------------------------------------------
__global__ void precompute_k(const float* __restrict__ feats,
                             const float* __restrict__ W1,
                             const float* __restrict__ b1) {
    int row = blockIdx.x;
    int c   = threadIdx.x;
    __shared__ float sf[FF];
    if (c < FF) sf[c] = feats[row * FF + c];
    __syncthreads();
    float accC = b1[c];
    float accN = 0.0f;
#pragma unroll
    for (int f = 0; f < FF; ++f) {
        float v = sf[f];
        accC = fmaf(v, W1[f * CC + c], accC);
        accN = fmaf(v, W1[(FF + f) * CC + c], accN);
    }
    g_Ac[row * CC + c] = accC;
    g_An[row * CC + c] = accN;
}

// ---------------------------------------------------------------------------
// Main: one block per (b,i). fp16 m16n8k16 mma, fragment-ready smem.
// smem words: Bf 8192 | X2f 8192 | X1f 4096 | misc 644  (~84.5 KB) -> 2 CTA/SM
// ---------------------------------------------------------------------------
__global__ __launch_bounds__(256, 2)
void edge_mlp_k(const int* __restrict__ mask,
                const float* __restrict__ b2,
                const float* __restrict__ b3,
                float* __restrict__ out) {
    extern __shared__ uint32_t smu[];
    uint32_t* sBf  = smu;                 // B-fragments (W2 then W3), fp16x2
    uint32_t* sX2f = sBf + 8192;          // X2 A-fragment order, fp16x2
    uint32_t* sX1f = sX2f + 8192;         // X1 pass tile (64 rows)
    float* sCi   = (float*)(sX1f + 4096);
    float* sB2   = sCi + 128;
    float* sB3   = sB2 + 128;
    float* sMj   = sB3 + 128;
    float* sS    = sMj + 128;
    float* sMsum = sS + 128;

    const int tid  = threadIdx.x;
    const int wid  = tid >> 5;
    const int lane = tid & 31;
    const int lr   = lane >> 2;
    const int lc   = lane & 3;
    const int bi   = blockIdx.x;
    const int b    = bi >> 7;
    const int i    = bi & 127;
    const int bbase = b * NN;

    // --- stage W2 fragments (coalesced), misc ---
    {
        const uint4* src = (const uint4*)g_W2h;
        uint4* dst = (uint4*)sBf;
#pragma unroll
        for (int u = 0; u < 8; ++u) dst[tid + u * 256] = src[tid + u * 256];
    }
    if (tid < 128) {
        sCi[tid] = g_Ac[bi * CC + tid];
        sB2[tid] = b2[tid];
        sB3[tid] = b3[tid];
        sS[tid]  = 0.0f;
        sMj[tid] = (mask[bbase + tid] != 0) ? 1.0f : 0.0f;
    }
    __syncthreads();
    if (tid == 0) {
        float s = 0.0f;
        for (int j = 0; j < NN; ++j) s += sMj[j];
        sMsum[0] = s;
    }

    // ================= GEMM1 over two 64-row passes =================
    const int mg = wid & 1;   // 32-row half within pass
    const int ng = wid >> 1;  // 32-col group (4 octets)

    for (int p = 0; p < 2; ++p) {
        const int jb = p * 64;
        // --- build X1f (64 rows, fp16 A-fragment order) ---
#pragma unroll
        for (int u = 0; u < 4; ++u) {
            int s   = tid + u * 256;          // 0..1023
            int mt  = s >> 8;
            int ks  = (s >> 5) & 7;
            int ln  = s & 31;
            int lrs = ln >> 2, lcs = ln & 3;
            int r0 = jb + mt * 16 + lrs, r1 = r0 + 8;
            int c0 = ks * 16 + 2 * lcs,  c1 = c0 + 8;
            float2 A0a = *(const float2*)&g_An[(bbase + r0) * CC + c0];
            float2 A0b = *(const float2*)&g_An[(bbase + r0) * CC + c1];
            float2 A1a = *(const float2*)&g_An[(bbase + r1) * CC + c0];
            float2 A1b = *(const float2*)&g_An[(bbase + r1) * CC + c1];
            float ci0 = sCi[c0], ci0b = sCi[c0 + 1];
            float ci1 = sCi[c1], ci1b = sCi[c1 + 1];
            uint4 v;
            v.x = pack2(lrelu(ci0 + A0a.x), lrelu(ci0b + A0a.y));
            v.y = pack2(lrelu(ci0 + A1a.x), lrelu(ci0b + A1a.y));
            v.z = pack2(lrelu(ci1 + A0b.x), lrelu(ci1b + A0b.y));
            v.w = pack2(lrelu(ci1 + A1b.x), lrelu(ci1b + A1b.y));
            *(uint4*)&sX1f[s * 4] = v;
        }
        __syncthreads();

        float acc[2][4][4];
#pragma unroll
        for (int mt = 0; mt < 2; ++mt)
#pragma unroll
            for (int of = 0; of < 4; ++of)
#pragma unroll
                for (int u = 0; u < 4; ++u) acc[mt][of][u] = 0.0f;

#pragma unroll
        for (int ks = 0; ks < 8; ++ks) {
            uint4 a0 = *(const uint4*)&sX1f[(((mg * 2 + 0) * 8 + ks) * 32 + lane) * 4];
            uint4 a1 = *(const uint4*)&sX1f[(((mg * 2 + 1) * 8 + ks) * 32 + lane) * 4];
#pragma unroll
            for (int of = 0; of < 4; ++of) {
                uint2 bb = *(const uint2*)&sBf[((ks * 16 + ng * 4 + of) * 32 + lane) * 2];
                mma_f16(acc[0][of], a0.x, a0.y, a0.z, a0.w, bb.x, bb.y);
                mma_f16(acc[1][of], a1.x, a1.y, a1.z, a1.w, bb.x, bb.y);
            }
        }

        // --- epilogue: bias+lrelu, pack fp16x2, write X2f A-frag order ---
#pragma unroll
        for (int mt = 0; mt < 2; ++mt) {
            int gmt = p * 4 + mg * 2 + mt;
#pragma unroll
            for (int of = 0; of < 4; ++of) {
                int oct = ng * 4 + of;
                int cb  = oct * 8 + 2 * lc;
                float e0 = lrelu(acc[mt][of][0] + sB2[cb]);
                float e1 = lrelu(acc[mt][of][1] + sB2[cb + 1]);
                float e2 = lrelu(acc[mt][of][2] + sB2[cb]);
                float e3 = lrelu(acc[mt][of][3] + sB2[cb + 1]);
                uint32_t base = ((gmt * 8 + (oct >> 1)) * 32 + lane) * 4 + (oct & 1) * 2;
                uint2 w;
                w.x = pack2(e0, e1);   // row lr
                w.y = pack2(e2, e3);   // row lr+8
                *(uint2*)&sX2f[base] = w;
            }
        }
        __syncthreads();
    }

    // --- swap to W3 fragments ---
    {
        const uint4* src = (const uint4*)g_W3h;
        uint4* dst = (uint4*)sBf;
#pragma unroll
        for (int u = 0; u < 8; ++u) dst[tid + u * 256] = src[tid + u * 256];
    }
    __syncthreads();

    // ===== GEMM2: S[c] = sum_j m_j * lrelu(X2 @ W3 + b3)[j,c] =====
    // warp tile 32 rows x 64 cols, processed as two 32-col sweeps
    {
        const int mg2 = wid & 3;   // 32-row group
        const int ng2 = wid >> 2;  // 64-col group

#pragma unroll
        for (int ch = 0; ch < 2; ++ch) {
            float acc2[2][4][4];
#pragma unroll
            for (int mt = 0; mt < 2; ++mt)
#pragma unroll
                for (int of = 0; of < 4; ++of)
#pragma unroll
                    for (int u = 0; u < 4; ++u) acc2[mt][of][u] = 0.0f;

#pragma unroll
            for (int ks = 0; ks < 8; ++ks) {
                uint4 a0 = *(const uint4*)&sX2f[(((mg2 * 2 + 0) * 8 + ks) * 32 + lane) * 4];
                uint4 a1 = *(const uint4*)&sX2f[(((mg2 * 2 + 1) * 8 + ks) * 32 + lane) * 4];
#pragma unroll
                for (int of = 0; of < 4; ++of) {
                    int oct = ng2 * 8 + ch * 4 + of;
                    uint2 bb = *(const uint2*)&sBf[((ks * 16 + oct) * 32 + lane) * 2];
                    mma_f16(acc2[0][of], a0.x, a0.y, a0.z, a0.w, bb.x, bb.y);
                    mma_f16(acc2[1][of], a1.x, a1.y, a1.z, a1.w, bb.x, bb.y);
                }
            }

            // mask-weighted column sums
            float cs[4][2];
#pragma unroll
            for (int of = 0; of < 4; ++of) { cs[of][0] = 0.0f; cs[of][1] = 0.0f; }
#pragma unroll
            for (int mt = 0; mt < 2; ++mt) {
                int r0 = mg2 * 32 + mt * 16 + lr, r1 = r0 + 8;
                float m0 = sMj[r0], m1 = sMj[r1];
#pragma unroll
                for (int of = 0; of < 4; ++of) {
                    int cb = (ng2 * 8 + ch * 4 + of) * 8 + 2 * lc;
                    cs[of][0] += m0 * lrelu(acc2[mt][of][0] + sB3[cb])
                               + m1 * lrelu(acc2[mt][of][2] + sB3[cb]);
                    cs[of][1] += m0 * lrelu(acc2[mt][of][1] + sB3[cb + 1])
                               + m1 * lrelu(acc2[mt][of][3] + sB3[cb + 1]);
                }
            }
#pragma unroll
            for (int of = 0; of < 4; ++of) {
#pragma unroll
                for (int o = 0; o < 2; ++o) {
                    float v = cs[of][o];
                    v += __shfl_xor_sync(0xffffffffu, v, 4);
                    v += __shfl_xor_sync(0xffffffffu, v, 8);
                    v += __shfl_xor_sync(0xffffffffu, v, 16);
                    if (lr == 0)
                        atomicAdd(&sS[(ng2 * 8 + ch * 4 + of) * 8 + 2 * lc + o], v);
                }
            }
        }
    }
    __syncthreads();

    // ======= final masked mean + multiply_no_nan + lrelu =======
    if (tid < 128) {
        float miv = sMj[i];
        float num = miv * sS[tid];
        float den = miv * sMsum[0];
        float o;
        if (num == 0.0f) o = 0.0f;
        else             o = num / (den == 0.0f ? 1.0f : den);
        out[bi * CC + tid] = lrelu(o);
    }
}

// ---------------------------------------------------------------------------
extern "C" void kernel_launch(void* const* d_in, const int* in_sizes, int n_in,
                              void* d_out, int out_size) {
    const float* feats = (const float*)d_in[0];
    const int*   mask  = (const int*)d_in[1];
    const float* W1    = (const float*)d_in[2];
    const float* b1    = (const float*)d_in[3];
    const float* W2    = (const float*)d_in[4];
    const float* b2    = (const float*)d_in[5];
    const float* W3    = (const float*)d_in[6];
    const float* b3    = (const float*)d_in[7];
    float* out = (float*)d_out;

    setup_wh_k<<<32, 256>>>(W2, W3);
    precompute_k<<<BN, 128>>>(feats, W1, b1);

    const size_t smem_bytes =
        (size_t)(8192 + 8192 + 4096 + 5 * 128 + 4) * sizeof(uint32_t);
    cudaFuncSetAttribute(edge_mlp_k,
                         cudaFuncAttributeMaxDynamicSharedMemorySize,
                         (int)smem_bytes);
    edge_mlp_k<<<BN, 256, smem_bytes>>>(mask, b2, b3, out);
}

// round 7
// speedup vs baseline: 6.8264x; 1.5459x over previous
#include <cuda_runtime.h>
#include <cuda_fp16.h>
#include <cstdint>

#define ALPHA 0.2f
#define NB 32
#define NN 128
#define FF 64
#define CC 128
#define BN (NB*NN)

static __device__ __forceinline__ float lrelu(float x) {
    return x >= 0.0f ? x : ALPHA * x;
}
static __device__ __forceinline__ uint32_t pack2(float lo, float hi) {
    __half2 h = __floats2half2_rn(lo, hi);
    return *(uint32_t*)&h;
}
static __device__ __forceinline__ void mma_f16(float c[4],
        uint32_t a0, uint32_t a1, uint32_t a2, uint32_t a3,
        uint32_t b0, uint32_t b1) {
    asm volatile(
        "mma.sync.aligned.m16n8k16.row.col.f32.f16.f16.f32 "
        "{%0,%1,%2,%3}, {%4,%5,%6,%7}, {%8,%9}, {%0,%1,%2,%3};\n"
        : "+f"(c[0]), "+f"(c[1]), "+f"(c[2]), "+f"(c[3])
        : "r"(a0), "r"(a1), "r"(a2), "r"(a3), "r"(b0), "r"(b1));
}

// Scratch
__device__ float g_Ac[BN * CC];
__device__ float g_An[BN * CC];
// fp16x2 B-fragment-ordered weights. Slot s = (ks*16+oct)*32+lane, ks in [0,8).
//   word s*2+0 = pack(W[k0  ][col], W[k0+1][col]),  k0 = ks*16+2*lc, col = oct*8+lr
//   word s*2+1 = pack(W[k0+8][col], W[k0+9][col])
__device__ uint32_t g_W2h[CC * CC / 2];
__device__ uint32_t g_W3h[CC * CC / 2];

// ---------------------------------------------------------------------------
// Prep: layer-1 partials (all blocks) + weight permute (blocks 0..63).
// Merged so each harness call is exactly 2 launches (ncu -s5 -> main kernel).
// ---------------------------------------------------------------------------
__global__ void prep_k(const float* __restrict__ feats,
                       const float* __restrict__ W1,
                       const float* __restrict__ b1,
                       const float* __restrict__ W2,
                       const float* __restrict__ W3) {
    // --- weight permute slice (8192 threads across first 64 blocks) ---
    if (blockIdx.x < 64) {
        int t = blockIdx.x * 128 + threadIdx.x;   // 0..8191
        const float* W   = (t & 4096) ? W3 : W2;
        uint32_t*    dst = (t & 4096) ? g_W3h : g_W2h;
        int s    = t & 4095;                       // slot = (ks*16+oct)*32+lane
        int ks   = s >> 9;
        int oct  = (s >> 5) & 15;
        int lane = s & 31;
        int lrw = lane >> 2, lcw = lane & 3;
        int col = oct * 8 + lrw;
        int k0  = ks * 16 + 2 * lcw;
        dst[s * 2]     = pack2(W[k0 * CC + col],       W[(k0 + 1) * CC + col]);
        dst[s * 2 + 1] = pack2(W[(k0 + 8) * CC + col], W[(k0 + 9) * CC + col]);
    }
    // --- per-node layer-1 partials ---
    int row = blockIdx.x;
    int c   = threadIdx.x;
    __shared__ float sf[FF];
    if (c < FF) sf[c] = feats[row * FF + c];
    __syncthreads();
    float accC = b1[c];
    float accN = 0.0f;
#pragma unroll
    for (int f = 0; f < FF; ++f) {
        float v = sf[f];
        accC = fmaf(v, W1[f * CC + c], accC);
        accN = fmaf(v, W1[(FF + f) * CC + c], accN);
    }
    g_Ac[row * CC + c] = accC;
    g_An[row * CC + c] = accN;
}

// ---------------------------------------------------------------------------
// Main: one block per (b,i). fp16 m16n8k16 mma, fragment-ready smem.
// smem words: Bf 8192 | X2f 8192 | X1f 2048 | misc 644 = 76.3 KB -> 3 CTA/SM
// ---------------------------------------------------------------------------
__global__ __launch_bounds__(256, 3)
void edge_mlp_k(const int* __restrict__ mask,
                const float* __restrict__ b2,
                const float* __restrict__ b3,
                float* __restrict__ out) {
    extern __shared__ uint32_t smu[];
    uint32_t* sBf  = smu;                 // B-fragments (W2 then W3), fp16x2
    uint32_t* sX2f = sBf + 8192;          // X2 A-fragment order, fp16x2
    uint32_t* sX1f = sX2f + 8192;         // X1 pass tile (32 rows)
    float* sCi   = (float*)(sX1f + 2048);
    float* sB2   = sCi + 128;
    float* sB3   = sB2 + 128;
    float* sMj   = sB3 + 128;
    float* sS    = sMj + 128;
    float* sMsum = sS + 128;

    const int tid  = threadIdx.x;
    const int wid  = tid >> 5;
    const int lane = tid & 31;
    const int lr   = lane >> 2;
    const int lc   = lane & 3;
    const int bi   = blockIdx.x;
    const int b    = bi >> 7;
    const int i    = bi & 127;
    const int bbase = b * NN;

    // --- stage W2 fragments (coalesced), misc ---
    {
        const uint4* src = (const uint4*)g_W2h;
        uint4* dst = (uint4*)sBf;
#pragma unroll
        for (int u = 0; u < 8; ++u) dst[tid + u * 256] = src[tid + u * 256];
    }
    if (tid < 128) {
        sCi[tid] = g_Ac[bi * CC + tid];
        sB2[tid] = b2[tid];
        sB3[tid] = b3[tid];
        sS[tid]  = 0.0f;
        sMj[tid] = (mask[bbase + tid] != 0) ? 1.0f : 0.0f;
    }
    __syncthreads();
    if (tid == 0) {
        float s = 0.0f;
        for (int j = 0; j < NN; ++j) s += sMj[j];
        sMsum[0] = s;
    }

    // ================= GEMM1 over four 32-row passes =================
    const int mg = wid & 1;   // 16-row mtile within pass
    const int ng = wid >> 1;  // 32-col group (4 octets)

    for (int p = 0; p < 4; ++p) {
        const int jb = p * 32;
        // --- build X1f (32 rows, fp16 A-fragment order); 512 slots ---
#pragma unroll
        for (int u = 0; u < 2; ++u) {
            int s   = tid + u * 256;          // 0..511
            int mt  = s >> 8;                 // 16-row mtile
            int ks  = (s >> 5) & 7;
            int ln  = s & 31;
            int lrs = ln >> 2, lcs = ln & 3;
            int r0 = jb + mt * 16 + lrs, r1 = r0 + 8;
            int c0 = ks * 16 + 2 * lcs,  c1 = c0 + 8;
            float2 A0a = *(const float2*)&g_An[(bbase + r0) * CC + c0];
            float2 A0b = *(const float2*)&g_An[(bbase + r0) * CC + c1];
            float2 A1a = *(const float2*)&g_An[(bbase + r1) * CC + c0];
            float2 A1b = *(const float2*)&g_An[(bbase + r1) * CC + c1];
            float ci0 = sCi[c0], ci0b = sCi[c0 + 1];
            float ci1 = sCi[c1], ci1b = sCi[c1 + 1];
            uint4 v;
            v.x = pack2(lrelu(ci0 + A0a.x), lrelu(ci0b + A0a.y));
            v.y = pack2(lrelu(ci0 + A1a.x), lrelu(ci0b + A1a.y));
            v.z = pack2(lrelu(ci1 + A0b.x), lrelu(ci1b + A0b.y));
            v.w = pack2(lrelu(ci1 + A1b.x), lrelu(ci1b + A1b.y));
            *(uint4*)&sX1f[s * 4] = v;
        }
        __syncthreads();

        float acc[4][4];
#pragma unroll
        for (int of = 0; of < 4; ++of)
#pragma unroll
            for (int u = 0; u < 4; ++u) acc[of][u] = 0.0f;

#pragma unroll
        for (int ks = 0; ks < 8; ++ks) {
            uint4 a = *(const uint4*)&sX1f[((mg * 8 + ks) * 32 + lane) * 4];
#pragma unroll
            for (int of = 0; of < 4; ++of) {
                uint2 bb = *(const uint2*)&sBf[((ks * 16 + ng * 4 + of) * 32 + lane) * 2];
                mma_f16(acc[of], a.x, a.y, a.z, a.w, bb.x, bb.y);
            }
        }

        // --- epilogue: bias+lrelu, pack fp16x2, write X2f A-frag order ---
        const int gmt = p * 2 + mg;
#pragma unroll
        for (int of = 0; of < 4; ++of) {
            int oct = ng * 4 + of;
            int cb  = oct * 8 + 2 * lc;
            float e0 = lrelu(acc[of][0] + sB2[cb]);
            float e1 = lrelu(acc[of][1] + sB2[cb + 1]);
            float e2 = lrelu(acc[of][2] + sB2[cb]);
            float e3 = lrelu(acc[of][3] + sB2[cb + 1]);
            uint32_t base = ((gmt * 8 + (oct >> 1)) * 32 + lane) * 4 + (oct & 1) * 2;
            uint2 w;
            w.x = pack2(e0, e1);   // row lr
            w.y = pack2(e2, e3);   // row lr+8
            *(uint2*)&sX2f[base] = w;
        }
        __syncthreads();
    }

    // --- swap to W3 fragments ---
    {
        const uint4* src = (const uint4*)g_W3h;
        uint4* dst = (uint4*)sBf;
#pragma unroll
        for (int u = 0; u < 8; ++u) dst[tid + u * 256] = src[tid + u * 256];
    }
    __syncthreads();

    // ===== GEMM2: S[c] = sum_j m_j * lrelu(X2 @ W3 + b3)[j,c] =====
    // warp tile 32 rows x 64 cols, processed as two 32-col sweeps
    {
        const int mg2 = wid & 3;   // 32-row group
        const int ng2 = wid >> 2;  // 64-col group

#pragma unroll
        for (int ch = 0; ch < 2; ++ch) {
            float acc2[2][4][4];
#pragma unroll
            for (int mt = 0; mt < 2; ++mt)
#pragma unroll
                for (int of = 0; of < 4; ++of)
#pragma unroll
                    for (int u = 0; u < 4; ++u) acc2[mt][of][u] = 0.0f;

#pragma unroll
            for (int ks = 0; ks < 8; ++ks) {
                uint4 a0 = *(const uint4*)&sX2f[(((mg2 * 2 + 0) * 8 + ks) * 32 + lane) * 4];
                uint4 a1 = *(const uint4*)&sX2f[(((mg2 * 2 + 1) * 8 + ks) * 32 + lane) * 4];
#pragma unroll
                for (int of = 0; of < 4; ++of) {
                    int oct = ng2 * 8 + ch * 4 + of;
                    uint2 bb = *(const uint2*)&sBf[((ks * 16 + oct) * 32 + lane) * 2];
                    mma_f16(acc2[0][of], a0.x, a0.y, a0.z, a0.w, bb.x, bb.y);
                    mma_f16(acc2[1][of], a1.x, a1.y, a1.z, a1.w, bb.x, bb.y);
                }
            }

            // mask-weighted column sums
            float cs[4][2];
#pragma unroll
            for (int of = 0; of < 4; ++of) { cs[of][0] = 0.0f; cs[of][1] = 0.0f; }
#pragma unroll
            for (int mt = 0; mt < 2; ++mt) {
                int r0 = mg2 * 32 + mt * 16 + lr, r1 = r0 + 8;
                float m0 = sMj[r0], m1 = sMj[r1];
#pragma unroll
                for (int of = 0; of < 4; ++of) {
                    int cb = (ng2 * 8 + ch * 4 + of) * 8 + 2 * lc;
                    cs[of][0] += m0 * lrelu(acc2[mt][of][0] + sB3[cb])
                               + m1 * lrelu(acc2[mt][of][2] + sB3[cb]);
                    cs[of][1] += m0 * lrelu(acc2[mt][of][1] + sB3[cb + 1])
                               + m1 * lrelu(acc2[mt][of][3] + sB3[cb + 1]);
                }
            }
#pragma unroll
            for (int of = 0; of < 4; ++of) {
#pragma unroll
                for (int o = 0; o < 2; ++o) {
                    float v = cs[of][o];
                    v += __shfl_xor_sync(0xffffffffu, v, 4);
                    v += __shfl_xor_sync(0xffffffffu, v, 8);
                    v += __shfl_xor_sync(0xffffffffu, v, 16);
                    if (lr == 0)
                        atomicAdd(&sS[(ng2 * 8 + ch * 4 + of) * 8 + 2 * lc + o], v);
                }
            }
        }
    }
    __syncthreads();

    // ======= final masked mean + multiply_no_nan + lrelu =======
    if (tid < 128) {
        float miv = sMj[i];
        float num = miv * sS[tid];
        float den = miv * sMsum[0];
        float o;
        if (num == 0.0f) o = 0.0f;
        else             o = num / (den == 0.0f ? 1.0f : den);
        out[bi * CC + tid] = lrelu(o);
    }
}

// ---------------------------------------------------------------------------
extern "C" void kernel_launch(void* const* d_in, const int* in_sizes, int n_in,
                              void* d_out, int out_size) {
    const float* feats = (const float*)d_in[0];
    const int*   mask  = (const int*)d_in[1];
    const float* W1    = (const float*)d_in[2];
    const float* b1    = (const float*)d_in[3];
    const float* W2    = (const float*)d_in[4];
    const float* b2    = (const float*)d_in[5];
    const float* W3    = (const float*)d_in[6];
    const float* b3    = (const float*)d_in[7];
    float* out = (float*)d_out;

    prep_k<<<BN, 128>>>(feats, W1, b1, W2, W3);

    const size_t smem_bytes =
        (size_t)(8192 + 8192 + 2048 + 5 * 128 + 4) * sizeof(uint32_t);
    cudaFuncSetAttribute(edge_mlp_k,
                         cudaFuncAttributeMaxDynamicSharedMemorySize,
                         (int)smem_bytes);
    edge_mlp_k<<<BN, 256, smem_bytes>>>(mask, b2, b3, out);
}